// round 5
// baseline (speedup 1.0000x reference)
#include <cuda_runtime.h>
#include <cuda_bf16.h>

// Depthwise conv1d, fixed shape: B=4, D=2048, L=8192, K=3, pad=1 -> L_out=L.
// out[b,d,l] = bias[d] + w[d,0]*x[l-1] + w[d,1]*x[l] + w[d,2]*x[l+1]
//
// Persistent-grid streaming kernel: 1184 CTAs (8/SM x 148 SMs) grid-stride
// over 8-element tiles (2x float4 per thread per iteration). Halos via warp
// shuffle; only warp-edge lanes touch memory for halos. Warp = 256
// contiguous elements per iteration, never straddles a row (256 | 8192).
// Loads/stores use streaming (.cs) policy - data is touched exactly once.

#define CONV_B 4
#define CONV_D 2048
#define CONV_L 8192
#define ELEMS_PER_THREAD 8
#define NUM_SMS 148
#define CTAS_PER_SM 8
#define THREADS_PER_CTA 256

__global__ __launch_bounds__(THREADS_PER_CTA) void dwconv1d_k3_kernel(
    const float* __restrict__ x,     // [B*D, L]
    const float* __restrict__ w,     // [D, 3]
    const float* __restrict__ bias,  // [D]
    float* __restrict__ out)         // [B*D, L]
{
    const unsigned total_tiles = (CONV_B * CONV_D * CONV_L) / ELEMS_PER_THREAD; // 8.39M
    const unsigned nthreads    = gridDim.x * THREADS_PER_CTA;
    const unsigned lane        = threadIdx.x & 31;

    unsigned tile = blockIdx.x * THREADS_PER_CTA + threadIdx.x;

    for (; tile < total_tiles; tile += nthreads) {
        const unsigned base = tile * ELEMS_PER_THREAD;       // element index < 2^27
        const unsigned l = base & (CONV_L - 1);              // pos within row
        const unsigned d = (base >> 13) & (CONV_D - 1);      // channel

        // uniform across the warp (warp spans 256 elems inside one row)
        const float w0 = __ldg(&w[d * 3 + 0]);
        const float w1 = __ldg(&w[d * 3 + 1]);
        const float w2 = __ldg(&w[d * 3 + 2]);
        const float bv = __ldg(&bias[d]);

        // 2 independent 128-bit streaming loads (touched exactly once)
        const float4* xv = reinterpret_cast<const float4*>(x + base);
        float4 v0 = __ldcs(&xv[0]);
        float4 v1 = __ldcs(&xv[1]);

        // halos via shuffle: lane-1 holds element base-1 (its v1.w),
        // lane+1 holds element base+8 (its v0.x)
        float left  = __shfl_up_sync(0xffffffffu, v1.w, 1);
        float right = __shfl_down_sync(0xffffffffu, v0.x, 1);
        if (lane == 0)
            left  = (l > 0) ? __ldg(x + base - 1) : 0.0f;
        if (lane == 31)
            right = (l + ELEMS_PER_THREAD < CONV_L) ? __ldg(x + base + ELEMS_PER_THREAD) : 0.0f;

        float4 o0, o1;
        o0.x = fmaf(w0, left,  fmaf(w1, v0.x, fmaf(w2, v0.y, bv)));
        o0.y = fmaf(w0, v0.x, fmaf(w1, v0.y, fmaf(w2, v0.z, bv)));
        o0.z = fmaf(w0, v0.y, fmaf(w1, v0.z, fmaf(w2, v0.w, bv)));
        o0.w = fmaf(w0, v0.z, fmaf(w1, v0.w, fmaf(w2, v1.x, bv)));

        o1.x = fmaf(w0, v0.w, fmaf(w1, v1.x, fmaf(w2, v1.y, bv)));
        o1.y = fmaf(w0, v1.x, fmaf(w1, v1.y, fmaf(w2, v1.z, bv)));
        o1.z = fmaf(w0, v1.y, fmaf(w1, v1.z, fmaf(w2, v1.w, bv)));
        o1.w = fmaf(w0, v1.z, fmaf(w1, v1.w, fmaf(w2, right, bv)));

        // streaming stores - no reuse, evict-first
        float4* ov = reinterpret_cast<float4*>(out + base);
        __stcs(&ov[0], o0);
        __stcs(&ov[1], o1);
    }
}

extern "C" void kernel_launch(void* const* d_in, const int* in_sizes, int n_in,
                              void* d_out, int out_size)
{
    const float* x    = (const float*)d_in[0];
    const float* w    = (const float*)d_in[1];
    const float* bias = (const float*)d_in[2];
    float*       out  = (float*)d_out;

    const int blocks = NUM_SMS * CTAS_PER_SM;   // 1184 — fills 64 warps/SM

    dwconv1d_k3_kernel<<<blocks, THREADS_PER_CTA>>>(x, w, bias, out);
}

// round 6
// speedup vs baseline: 1.1050x; 1.1050x over previous
#include <cuda_runtime.h>
#include <cuda_bf16.h>

// Depthwise conv1d, fixed shape: B=4, D=2048, L=8192, K=3, pad=1 -> L_out=L.
// out[b,d,l] = bias[d] + w[d,0]*x[l-1] + w[d,1]*x[l] + w[d,2]*x[l+1]
//
// Dual-stream one-shot kernel: each thread handles TWO 8-element tiles
// (2x float4 each) from tensor halves 128MB apart. 4 independent LDG.128
// issued up front -> per-thread MLP=4 across two DRAM streams, with two
// independent FMA/store chains overlapping each other's load latency.
// Halos via warp shuffle per stream; only warp-edge lanes touch memory.
// Warp = 256 contiguous elements per stream, never straddles a row.

#define CONV_B 4
#define CONV_D 2048
#define CONV_L 8192
#define ELEMS_PER_THREAD 8
#define TOTAL_ELEMS (CONV_B * CONV_D * CONV_L)      // 67,108,864
#define HALF_ELEMS  (TOTAL_ELEMS / 2)               // 33,554,432

__global__ __launch_bounds__(256) void dwconv1d_k3_kernel(
    const float* __restrict__ x,     // [B*D, L]
    const float* __restrict__ w,     // [D, 3]
    const float* __restrict__ bias,  // [D]
    float* __restrict__ out)         // [B*D, L]
{
    const unsigned tid   = blockIdx.x * blockDim.x + threadIdx.x;
    const unsigned lane  = threadIdx.x & 31;

    const unsigned baseA = tid * ELEMS_PER_THREAD;       // first half
    const unsigned baseB = baseA + HALF_ELEMS;           // second half

    // per-stream position / channel (HALF_ELEMS is a multiple of L and of L*D? 
    // 33.55M / 8192 = 4096 rows -> yes, row-aligned, so masks stay valid)
    const unsigned lA = baseA & (CONV_L - 1);
    const unsigned dA = (baseA >> 13) & (CONV_D - 1);
    const unsigned lB = baseB & (CONV_L - 1);
    const unsigned dB = (baseB >> 13) & (CONV_D - 1);

    // issue all 4 payload loads back-to-back (MLP = 4, two DRAM streams)
    const float4* xvA = reinterpret_cast<const float4*>(x + baseA);
    const float4* xvB = reinterpret_cast<const float4*>(x + baseB);
    float4 a0 = xvA[0];
    float4 a1 = xvA[1];
    float4 b0 = xvB[0];
    float4 b1 = xvB[1];

    // weights/bias (uniform across warp per stream)
    const float wA0 = __ldg(&w[dA * 3 + 0]);
    const float wA1 = __ldg(&w[dA * 3 + 1]);
    const float wA2 = __ldg(&w[dA * 3 + 2]);
    const float bvA = __ldg(&bias[dA]);
    const float wB0 = __ldg(&w[dB * 3 + 0]);
    const float wB1 = __ldg(&w[dB * 3 + 1]);
    const float wB2 = __ldg(&w[dB * 3 + 2]);
    const float bvB = __ldg(&bias[dB]);

    // halos via shuffle (per stream)
    float leftA  = __shfl_up_sync(0xffffffffu, a1.w, 1);
    float rightA = __shfl_down_sync(0xffffffffu, a0.x, 1);
    float leftB  = __shfl_up_sync(0xffffffffu, b1.w, 1);
    float rightB = __shfl_down_sync(0xffffffffu, b0.x, 1);
    if (lane == 0) {
        leftA = (lA > 0) ? __ldg(x + baseA - 1) : 0.0f;
        leftB = (lB > 0) ? __ldg(x + baseB - 1) : 0.0f;
    }
    if (lane == 31) {
        rightA = (lA + ELEMS_PER_THREAD < CONV_L) ? __ldg(x + baseA + ELEMS_PER_THREAD) : 0.0f;
        rightB = (lB + ELEMS_PER_THREAD < CONV_L) ? __ldg(x + baseB + ELEMS_PER_THREAD) : 0.0f;
    }

    // stream A compute + store
    {
        float4 o0, o1;
        o0.x = fmaf(wA0, leftA, fmaf(wA1, a0.x, fmaf(wA2, a0.y, bvA)));
        o0.y = fmaf(wA0, a0.x, fmaf(wA1, a0.y, fmaf(wA2, a0.z, bvA)));
        o0.z = fmaf(wA0, a0.y, fmaf(wA1, a0.z, fmaf(wA2, a0.w, bvA)));
        o0.w = fmaf(wA0, a0.z, fmaf(wA1, a0.w, fmaf(wA2, a1.x, bvA)));
        o1.x = fmaf(wA0, a0.w, fmaf(wA1, a1.x, fmaf(wA2, a1.y, bvA)));
        o1.y = fmaf(wA0, a1.x, fmaf(wA1, a1.y, fmaf(wA2, a1.z, bvA)));
        o1.z = fmaf(wA0, a1.y, fmaf(wA1, a1.z, fmaf(wA2, a1.w, bvA)));
        o1.w = fmaf(wA0, a1.z, fmaf(wA1, a1.w, fmaf(wA2, rightA, bvA)));
        float4* ov = reinterpret_cast<float4*>(out + baseA);
        __stcs(&ov[0], o0);
        __stcs(&ov[1], o1);
    }

    // stream B compute + store
    {
        float4 o0, o1;
        o0.x = fmaf(wB0, leftB, fmaf(wB1, b0.x, fmaf(wB2, b0.y, bvB)));
        o0.y = fmaf(wB0, b0.x, fmaf(wB1, b0.y, fmaf(wB2, b0.z, bvB)));
        o0.z = fmaf(wB0, b0.y, fmaf(wB1, b0.z, fmaf(wB2, b0.w, bvB)));
        o0.w = fmaf(wB0, b0.z, fmaf(wB1, b0.w, fmaf(wB2, b1.x, bvB)));
        o1.x = fmaf(wB0, b0.w, fmaf(wB1, b1.x, fmaf(wB2, b1.y, bvB)));
        o1.y = fmaf(wB0, b1.x, fmaf(wB1, b1.y, fmaf(wB2, b1.z, bvB)));
        o1.z = fmaf(wB0, b1.y, fmaf(wB1, b1.z, fmaf(wB2, b1.w, bvB)));
        o1.w = fmaf(wB0, b1.z, fmaf(wB1, b1.w, fmaf(wB2, rightB, bvB)));
        float4* ov = reinterpret_cast<float4*>(out + baseB);
        __stcs(&ov[0], o0);
        __stcs(&ov[1], o1);
    }
}

extern "C" void kernel_launch(void* const* d_in, const int* in_sizes, int n_in,
                              void* d_out, int out_size)
{
    const float* x    = (const float*)d_in[0];
    const float* w    = (const float*)d_in[1];
    const float* bias = (const float*)d_in[2];
    float*       out  = (float*)d_out;

    const int threads = 256;
    const int blocks  = HALF_ELEMS / (threads * ELEMS_PER_THREAD);  // 16384

    dwconv1d_k3_kernel<<<blocks, threads>>>(x, w, bias, out);
}